// round 15
// baseline (speedup 1.0000x reference)
#include <cuda_runtime.h>
#include <stdint.h>

// Energy4D: 4x multi-resolution hash-grid encodings (instant-NGP style).
// L=16 levels, F=2 feats, HMAP=2^19, BASE=32, GROWTH=2 -> res_l = 32<<l.
//
// R14 -> R15: sort dedup gain on encode is real (~32us) but overhead (~38us)
// ate it. Cut overhead to ~15us: scatter 4pts/thread (atomic-latency bound),
// key_hist 2pts/thread, scanB as single-warp shfl scan, zero via int4.
// Encode kernels unchanged (perm for levels 0-11; identity for <12,4> which
// sits at the L1-miss-throughput floor; evict-last gathers; streaming sts).
//
// Numerics must match XLA bit-for-bit: x/const -> x*rn(1/const);
// w = rn(u*resm1) - p0_clip; all __f*_rn (immune to --use_fast_math).

constexpr unsigned HMASK = (1u << 19) - 1u;
constexpr unsigned P1 = 2654435761u;
constexpr unsigned P2 = 805459861u;
constexpr int NPTS = 262144;
constexpr int NBINS = 65536;

__device__ int g_hist[NBINS];
__device__ int g_bsum[256];
__device__ unsigned short g_key[NPTS];
__device__ int g_perm[NPTS];

__device__ __host__ constexpr int level_offset(int l) {
    return (l == 0) ? 0 : (l == 1) ? 32768 : 294912 + (l - 2) * 524288;
}

__device__ __forceinline__ float clip01(float v) {
    return fminf(fmaxf(v, 0.0f), 1.0f);
}

__device__ __forceinline__ float2 ldg_tbl(const float2* p, uint64_t pol) {
    float2 v;
    asm("ld.global.nc.L2::cache_hint.v2.f32 {%0,%1}, [%2], %3;"
        : "=f"(v.x), "=f"(v.y) : "l"(p), "l"(pol));
    return v;
}

__device__ __forceinline__ void st_cs4(float4* p, float4 v) {
    asm volatile("st.global.cs.v4.f32 [%0], {%1,%2,%3,%4};"
                 :: "l"(p), "f"(v.x), "f"(v.y), "f"(v.z), "f"(v.w) : "memory");
}

__device__ __forceinline__ void compute_u(float4 c, float4 r,
                                          float& ux, float& uy, float& uz, float& ut) {
    const float R180   = 1.0f / 180.0f;
    const float R360   = 1.0f / 360.0f;
    const float R20000 = 1.0f / 20000.0f;
    float nx = clip01(__fmul_rn(__fadd_rn(__fsub_rn(c.x, r.x), 90.0f),    R180));
    float ny = clip01(__fmul_rn(__fadd_rn(__fsub_rn(c.y, r.y), 180.0f),   R360));
    float nz = clip01(__fmul_rn(__fadd_rn(__fsub_rn(c.z, r.z), 11000.0f), R20000));
    float nt = clip01(__fsub_rn(c.w, r.w));
    float tsn = __fmul_rn(__fsub_rn(__fmul_rn(nt, 2.0f), 1.0f), 0.9f);
    ux = clip01(__fmul_rn(__fadd_rn(nx,  1.0f), 0.5f));
    uy = clip01(__fmul_rn(__fadd_rn(ny,  1.0f), 0.5f));
    uz = clip01(__fmul_rn(__fadd_rn(nz,  1.0f), 0.5f));
    ut = clip01(__fmul_rn(__fadd_rn(tsn, 1.0f), 0.5f));
}

// ---------------- sort: zero -> key+hist -> scan(A,B,C) -> scatter --------

__global__ void zero_hist_kernel() {      // 64 blocks x 256 thr, int4 writes
    ((int4*)g_hist)[blockIdx.x * blockDim.x + threadIdx.x] = make_int4(0, 0, 0, 0);
}

__device__ __forceinline__ int quantn(float v, float lo, float inv_w, int maxq) {
    int q = (int)((v - lo) * inv_w);
    return min(max(q, 0), maxq);
}

__device__ __forceinline__ unsigned make_key(float ux, float uy, float uz, float ut) {
    // bits: x=3, y=3, z=3, t=7 (t spans ~16x more cells than x per level)
    unsigned qx = quantn(ux, 0.7444f, 8.0f   / 0.0112f, 7);
    unsigned qy = quantn(uy, 0.7472f, 8.0f   / 0.0056f, 7);
    unsigned qz = quantn(uz, 0.7700f, 8.0f   / 0.0100f, 7);
    unsigned qt = quantn(ut, 0.0500f, 128.0f / 0.1800f, 127);
    // interleave LSB->MSB: t0 t1 x0 y0 z0 t2 t3 x1 y1 z1 t4 t5 x2 y2 z2 t6
    return (qt & 3u)
        | ((qx & 1u) << 2) | ((qy & 1u) << 3) | ((qz & 1u) << 4)
        | (((qt >> 2) & 3u) << 5)
        | (((qx >> 1) & 1u) << 7) | (((qy >> 1) & 1u) << 8) | (((qz >> 1) & 1u) << 9)
        | (((qt >> 4) & 3u) << 10)
        | (((qx >> 2) & 1u) << 12) | (((qy >> 2) & 1u) << 13) | (((qz >> 2) & 1u) << 14)
        | (((qt >> 6) & 1u) << 15);
}

__global__ void key_hist_kernel(const float4* __restrict__ coords,
                                const float4* __restrict__ refc) {
    int base = blockIdx.x * (blockDim.x * 2) + threadIdx.x;
    #pragma unroll
    for (int k = 0; k < 2; ++k) {
        int i = base + k * blockDim.x;
        float ux, uy, uz, ut;
        compute_u(coords[i], refc[i], ux, uy, uz, ut);
        unsigned key = make_key(ux, uy, uz, ut);
        g_key[i] = (unsigned short)key;
        atomicAdd(&g_hist[key], 1);
    }
}

// A: per-block sums of 256-bin chunks (coalesced)
__global__ __launch_bounds__(256) void scanA_kernel() {
    __shared__ int s[256];
    int t = threadIdx.x;
    int v = g_hist[blockIdx.x * 256 + t];
    s[t] = v;
    __syncthreads();
    for (int off = 128; off > 0; off >>= 1) {
        if (t < off) s[t] += s[t + off];
        __syncthreads();
    }
    if (t == 0) g_bsum[blockIdx.x] = s[0];
}

// B: exclusive scan of 256 block sums — one warp, 8 elems/lane + shfl scan
__global__ __launch_bounds__(32) void scanB_kernel() {
    int lane = threadIdx.x;
    int base = lane * 8;
    int v[8];
    int s = 0;
    #pragma unroll
    for (int k = 0; k < 8; ++k) { v[k] = g_bsum[base + k]; s += v[k]; }
    int incl = s;
    #pragma unroll
    for (int off = 1; off < 32; off <<= 1) {
        int x = __shfl_up_sync(0xFFFFFFFFu, incl, off);
        if (lane >= off) incl += x;
    }
    int run = incl - s;  // exclusive prefix of this lane's chunk
    #pragma unroll
    for (int k = 0; k < 8; ++k) { g_bsum[base + k] = run; run += v[k]; }
}

// C: per-chunk exclusive scan + chunk offset (coalesced)
__global__ __launch_bounds__(256) void scanC_kernel() {
    __shared__ int s[256];
    int t = threadIdx.x;
    int bin = blockIdx.x * 256 + t;
    int v = g_hist[bin];
    s[t] = v;
    __syncthreads();
    for (int off = 1; off < 256; off <<= 1) {
        int x = (t >= off) ? s[t - off] : 0;
        __syncthreads();
        s[t] += x;
        __syncthreads();
    }
    g_hist[bin] = s[t] - v + g_bsum[blockIdx.x];
}

// scatter: 4 points per thread — 4 independent atomic chains (latency-bound)
__global__ void scatter_kernel() {
    int base = (blockIdx.x * blockDim.x + threadIdx.x) * 4;
    #pragma unroll
    for (int k = 0; k < 4; ++k) {
        int i = base + k;
        int pos = atomicAdd(&g_hist[g_key[i]], 1);
        g_perm[pos] = i;
    }
}

// ---------------- main encode kernels ----------------

template <int L0, int NLEV, bool USE_PERM>
__global__ __launch_bounds__(256) void energy4d_group_kernel(
    const float4* __restrict__ coords,
    const float4* __restrict__ refc,
    const float2* __restrict__ t0,
    const float2* __restrict__ t1,
    const float2* __restrict__ t2,
    const float2* __restrict__ t3,
    float2* __restrict__ out)   // out as float2: elem = pt*64 + e*16 + l
{
    const int warp = threadIdx.x >> 5;
    const int lane = threadIdx.x & 31;
    const int e    = warp & 3;                               // encoding id
    const int slot = (blockIdx.x * 2 + (warp >> 2)) * 32 + lane;
    const int pt   = USE_PERM ? g_perm[slot] : slot;

    uint64_t pol;
    asm("createpolicy.fractional.L2::evict_last.b64 %0, 1.0;" : "=l"(pol));

    float ux, uy, uz, ut;
    compute_u(coords[pt], refc[pt], ux, uy, uz, ut);

    // encoding dim selection: e0=(x,y,z) e1=(x,y,t) e2=(y,z,t) e3=(x,z,t)
    const float ua = (e == 2) ? uy : ux;
    const float ub = (e <= 1) ? uy : uz;
    const float uc = (e == 0) ? uz : ut;
    const float2* __restrict__ tbl =
        (e == 0) ? t0 : (e == 1) ? t1 : (e == 2) ? t2 : t3;

    float2 acc[NLEV];

    #pragma unroll
    for (int j = 0; j < NLEV; ++j) {
        const int   l     = L0 + j;
        const int   res   = 32 << l;
        const float resm1 = (float)(res - 1);
        const int   off   = level_offset(l);

        float pa = __fmul_rn(ua, resm1);
        float pb = __fmul_rn(ub, resm1);
        float pc = __fmul_rn(uc, resm1);
        int a0 = min(max((int)floorf(pa), 0), res - 2);
        int b0 = min(max((int)floorf(pb), 0), res - 2);
        int c0 = min(max((int)floorf(pc), 0), res - 2);
        float wa = __fsub_rn(pa, (float)a0);
        float wb = __fsub_rn(pb, (float)b0);
        float wc = __fsub_rn(pc, (float)c0);

        int idx[8];
        if (l >= 2) {
            unsigned ha0 = (unsigned)a0,      ha1 = ha0 + 1u;
            unsigned hb0 = (unsigned)b0 * P1, hb1 = hb0 + P1;
            unsigned hc0 = (unsigned)c0 * P2, hc1 = hc0 + P2;
            idx[0] = (int)((ha0 ^ hb0 ^ hc0) & HMASK) + off;
            idx[1] = (int)((ha1 ^ hb0 ^ hc0) & HMASK) + off;
            idx[2] = (int)((ha0 ^ hb1 ^ hc0) & HMASK) + off;
            idx[3] = (int)((ha1 ^ hb1 ^ hc0) & HMASK) + off;
            idx[4] = (int)((ha0 ^ hb0 ^ hc1) & HMASK) + off;
            idx[5] = (int)((ha1 ^ hb0 ^ hc1) & HMASK) + off;
            idx[6] = (int)((ha0 ^ hb1 ^ hc1) & HMASK) + off;
            idx[7] = (int)((ha1 ^ hb1 ^ hc1) & HMASK) + off;
        } else {
            const int rr = res * res;
            int base = a0 + res * (b0 + res * c0) + off;
            idx[0] = base;
            idx[1] = base + 1;
            idx[2] = base + res;
            idx[3] = base + res + 1;
            idx[4] = base + rr;
            idx[5] = base + rr + 1;
            idx[6] = base + rr + res;
            idx[7] = base + rr + res + 1;
        }

        float2 f[8];
        #pragma unroll
        for (int i = 0; i < 8; ++i) f[i] = ldg_tbl(&tbl[idx[i]], pol);

        const float oma = __fsub_rn(1.0f, wa);
        const float omb = __fsub_rn(1.0f, wb);
        const float omc = __fsub_rn(1.0f, wc);
        float accx = 0.0f, accy = 0.0f;
        #pragma unroll
        for (int i = 0; i < 8; ++i) {
            float cwa = (i & 1) ? wa : oma;
            float cwb = (i & 2) ? wb : omb;
            float cwc = (i & 4) ? wc : omc;
            float cw  = __fmul_rn(__fmul_rn(cwa, cwb), cwc);
            accx = __fadd_rn(accx, __fmul_rn(f[i].x, cw));
            accy = __fadd_rn(accy, __fmul_rn(f[i].y, cw));
        }
        acc[j] = make_float2(accx, accy);
    }

    float2* optr = out + (size_t)pt * 64 + (size_t)e * 16 + L0;
    #pragma unroll
    for (int j = 0; j < NLEV; j += 2) {
        st_cs4((float4*)(optr + j),
               make_float4(acc[j].x, acc[j].y, acc[j + 1].x, acc[j + 1].y));
    }
}

extern "C" void kernel_launch(void* const* d_in, const int* in_sizes, int n_in,
                              void* d_out, int out_size) {
    const int n = in_sizes[0] / 4;          // number of points (262144)
    const float4* coords = (const float4*)d_in[0];
    const float4* refc   = (const float4*)d_in[1];
    const float2* t0 = (const float2*)d_in[2];
    const float2* t1 = (const float2*)d_in[3];
    const float2* t2 = (const float2*)d_in[4];
    const float2* t3 = (const float2*)d_in[5];
    float2* out = (float2*)d_out;

    // counting sort by 16-bit Morton key (parallel, coalesced, low overhead)
    zero_hist_kernel<<<NBINS / 4 / 256, 256>>>();
    key_hist_kernel<<<n / 512, 256>>>(coords, refc);
    scanA_kernel<<<256, 256>>>();
    scanB_kernel<<<1, 32>>>();
    scanC_kernel<<<256, 256>>>();
    scatter_kernel<<<n / 4 / 256, 256>>>();

    dim3 block(256);                        // 8 warps = 2 pt-groups x 4 encodings
    dim3 grid(n / 64);
    energy4d_group_kernel<0,  4, true ><<<grid, block>>>(coords, refc, t0, t1, t2, t3, out);
    energy4d_group_kernel<4,  4, true ><<<grid, block>>>(coords, refc, t0, t1, t2, t3, out);
    energy4d_group_kernel<8,  4, true ><<<grid, block>>>(coords, refc, t0, t1, t2, t3, out);
    energy4d_group_kernel<12, 4, false><<<grid, block>>>(coords, refc, t0, t1, t2, t3, out);
}

// round 16
// speedup vs baseline: 1.0182x; 1.0182x over previous
#include <cuda_runtime.h>
#include <stdint.h>

// Energy4D: 4x multi-resolution hash-grid encodings (instant-NGP style).
// L=16 levels, F=2 feats, HMAP=2^19, BASE=32, GROWTH=2 -> res_l = 32<<l.
//
// R15 -> R16: the sort's ~32us encode gain was eaten by ~30us of per-node
// launch latency (scanB: 4.3us for one warp = pure launch cost). Fix by
// GRAPH PARALLELISM: enc<12,4> (109us, identity order, at its L1-miss
// floor) is independent of the sort chain -> run it on a forked side stream
// concurrent with sort + perm-encodes; launch latencies hide under it.
// Also drop the zero kernel: g_cnt is read+rezeroed by scanC each run
// (zero-init on first run, pipeline restores zeros every run).
//
// Numerics must match XLA bit-for-bit: x/const -> x*rn(1/const);
// w = rn(u*resm1) - p0_clip; all __f*_rn (immune to --use_fast_math).

constexpr unsigned HMASK = (1u << 19) - 1u;
constexpr unsigned P1 = 2654435761u;
constexpr unsigned P2 = 805459861u;
constexpr int NPTS = 262144;
constexpr int NBINS = 65536;

__device__ int g_cnt[NBINS];    // counts: zero at start of every run
__device__ int g_off[NBINS];    // scatter offsets (rewritten every run)
__device__ int g_bsum[256];
__device__ unsigned short g_key[NPTS];
__device__ int g_perm[NPTS];

__device__ __host__ constexpr int level_offset(int l) {
    return (l == 0) ? 0 : (l == 1) ? 32768 : 294912 + (l - 2) * 524288;
}

__device__ __forceinline__ float clip01(float v) {
    return fminf(fmaxf(v, 0.0f), 1.0f);
}

__device__ __forceinline__ float2 ldg_tbl(const float2* p, uint64_t pol) {
    float2 v;
    asm("ld.global.nc.L2::cache_hint.v2.f32 {%0,%1}, [%2], %3;"
        : "=f"(v.x), "=f"(v.y) : "l"(p), "l"(pol));
    return v;
}

__device__ __forceinline__ void st_cs4(float4* p, float4 v) {
    asm volatile("st.global.cs.v4.f32 [%0], {%1,%2,%3,%4};"
                 :: "l"(p), "f"(v.x), "f"(v.y), "f"(v.z), "f"(v.w) : "memory");
}

__device__ __forceinline__ void compute_u(float4 c, float4 r,
                                          float& ux, float& uy, float& uz, float& ut) {
    const float R180   = 1.0f / 180.0f;
    const float R360   = 1.0f / 360.0f;
    const float R20000 = 1.0f / 20000.0f;
    float nx = clip01(__fmul_rn(__fadd_rn(__fsub_rn(c.x, r.x), 90.0f),    R180));
    float ny = clip01(__fmul_rn(__fadd_rn(__fsub_rn(c.y, r.y), 180.0f),   R360));
    float nz = clip01(__fmul_rn(__fadd_rn(__fsub_rn(c.z, r.z), 11000.0f), R20000));
    float nt = clip01(__fsub_rn(c.w, r.w));
    float tsn = __fmul_rn(__fsub_rn(__fmul_rn(nt, 2.0f), 1.0f), 0.9f);
    ux = clip01(__fmul_rn(__fadd_rn(nx,  1.0f), 0.5f));
    uy = clip01(__fmul_rn(__fadd_rn(ny,  1.0f), 0.5f));
    uz = clip01(__fmul_rn(__fadd_rn(nz,  1.0f), 0.5f));
    ut = clip01(__fmul_rn(__fadd_rn(tsn, 1.0f), 0.5f));
}

// ---------------- sort: key+hist -> scanA/B/C -> scatter ----------------

__device__ __forceinline__ int quantn(float v, float lo, float inv_w, int maxq) {
    int q = (int)((v - lo) * inv_w);
    return min(max(q, 0), maxq);
}

__device__ __forceinline__ unsigned make_key(float ux, float uy, float uz, float ut) {
    // bits: x=3, y=3, z=3, t=7 (t spans ~16x more cells than x per level)
    unsigned qx = quantn(ux, 0.7444f, 8.0f   / 0.0112f, 7);
    unsigned qy = quantn(uy, 0.7472f, 8.0f   / 0.0056f, 7);
    unsigned qz = quantn(uz, 0.7700f, 8.0f   / 0.0100f, 7);
    unsigned qt = quantn(ut, 0.0500f, 128.0f / 0.1800f, 127);
    return (qt & 3u)
        | ((qx & 1u) << 2) | ((qy & 1u) << 3) | ((qz & 1u) << 4)
        | (((qt >> 2) & 3u) << 5)
        | (((qx >> 1) & 1u) << 7) | (((qy >> 1) & 1u) << 8) | (((qz >> 1) & 1u) << 9)
        | (((qt >> 4) & 3u) << 10)
        | (((qx >> 2) & 1u) << 12) | (((qy >> 2) & 1u) << 13) | (((qz >> 2) & 1u) << 14)
        | (((qt >> 6) & 1u) << 15);
}

__global__ void key_hist_kernel(const float4* __restrict__ coords,
                                const float4* __restrict__ refc) {
    int base = blockIdx.x * (blockDim.x * 2) + threadIdx.x;
    #pragma unroll
    for (int k = 0; k < 2; ++k) {
        int i = base + k * blockDim.x;
        float ux, uy, uz, ut;
        compute_u(coords[i], refc[i], ux, uy, uz, ut);
        unsigned key = make_key(ux, uy, uz, ut);
        g_key[i] = (unsigned short)key;
        atomicAdd(&g_cnt[key], 1);
    }
}

// A: per-block sums of 256-bin chunks (read-only on g_cnt)
__global__ __launch_bounds__(256) void scanA_kernel() {
    __shared__ int s[256];
    int t = threadIdx.x;
    s[t] = g_cnt[blockIdx.x * 256 + t];
    __syncthreads();
    for (int off = 128; off > 0; off >>= 1) {
        if (t < off) s[t] += s[t + off];
        __syncthreads();
    }
    if (t == 0) g_bsum[blockIdx.x] = s[0];
}

// B: exclusive scan of 256 block sums — one warp, shfl
__global__ __launch_bounds__(32) void scanB_kernel() {
    int lane = threadIdx.x;
    int base = lane * 8;
    int v[8];
    int s = 0;
    #pragma unroll
    for (int k = 0; k < 8; ++k) { v[k] = g_bsum[base + k]; s += v[k]; }
    int incl = s;
    #pragma unroll
    for (int off = 1; off < 32; off <<= 1) {
        int x = __shfl_up_sync(0xFFFFFFFFu, incl, off);
        if (lane >= off) incl += x;
    }
    int run = incl - s;
    #pragma unroll
    for (int k = 0; k < 8; ++k) { g_bsum[base + k] = run; run += v[k]; }
}

// C: per-chunk exclusive scan + offset -> g_off; rezero g_cnt for next run
__global__ __launch_bounds__(256) void scanC_kernel() {
    __shared__ int s[256];
    int t = threadIdx.x;
    int bin = blockIdx.x * 256 + t;
    int v = g_cnt[bin];
    g_cnt[bin] = 0;                      // restore zeros for next replay
    s[t] = v;
    __syncthreads();
    for (int off = 1; off < 256; off <<= 1) {
        int x = (t >= off) ? s[t - off] : 0;
        __syncthreads();
        s[t] += x;
        __syncthreads();
    }
    g_off[bin] = s[t] - v + g_bsum[blockIdx.x];
}

// scatter: 4 points per thread — independent atomic chains
__global__ void scatter_kernel() {
    int base = (blockIdx.x * blockDim.x + threadIdx.x) * 4;
    #pragma unroll
    for (int k = 0; k < 4; ++k) {
        int i = base + k;
        int pos = atomicAdd(&g_off[g_key[i]], 1);
        g_perm[pos] = i;
    }
}

// ---------------- main encode kernels ----------------

template <int L0, int NLEV, bool USE_PERM>
__global__ __launch_bounds__(256) void energy4d_group_kernel(
    const float4* __restrict__ coords,
    const float4* __restrict__ refc,
    const float2* __restrict__ t0,
    const float2* __restrict__ t1,
    const float2* __restrict__ t2,
    const float2* __restrict__ t3,
    float2* __restrict__ out)   // out as float2: elem = pt*64 + e*16 + l
{
    const int warp = threadIdx.x >> 5;
    const int lane = threadIdx.x & 31;
    const int e    = warp & 3;                               // encoding id
    const int slot = (blockIdx.x * 2 + (warp >> 2)) * 32 + lane;
    const int pt   = USE_PERM ? g_perm[slot] : slot;

    uint64_t pol;
    asm("createpolicy.fractional.L2::evict_last.b64 %0, 1.0;" : "=l"(pol));

    float ux, uy, uz, ut;
    compute_u(coords[pt], refc[pt], ux, uy, uz, ut);

    // encoding dim selection: e0=(x,y,z) e1=(x,y,t) e2=(y,z,t) e3=(x,z,t)
    const float ua = (e == 2) ? uy : ux;
    const float ub = (e <= 1) ? uy : uz;
    const float uc = (e == 0) ? uz : ut;
    const float2* __restrict__ tbl =
        (e == 0) ? t0 : (e == 1) ? t1 : (e == 2) ? t2 : t3;

    float2 acc[NLEV];

    #pragma unroll
    for (int j = 0; j < NLEV; ++j) {
        const int   l     = L0 + j;
        const int   res   = 32 << l;
        const float resm1 = (float)(res - 1);
        const int   off   = level_offset(l);

        float pa = __fmul_rn(ua, resm1);
        float pb = __fmul_rn(ub, resm1);
        float pc = __fmul_rn(uc, resm1);
        int a0 = min(max((int)floorf(pa), 0), res - 2);
        int b0 = min(max((int)floorf(pb), 0), res - 2);
        int c0 = min(max((int)floorf(pc), 0), res - 2);
        float wa = __fsub_rn(pa, (float)a0);
        float wb = __fsub_rn(pb, (float)b0);
        float wc = __fsub_rn(pc, (float)c0);

        int idx[8];
        if (l >= 2) {
            unsigned ha0 = (unsigned)a0,      ha1 = ha0 + 1u;
            unsigned hb0 = (unsigned)b0 * P1, hb1 = hb0 + P1;
            unsigned hc0 = (unsigned)c0 * P2, hc1 = hc0 + P2;
            idx[0] = (int)((ha0 ^ hb0 ^ hc0) & HMASK) + off;
            idx[1] = (int)((ha1 ^ hb0 ^ hc0) & HMASK) + off;
            idx[2] = (int)((ha0 ^ hb1 ^ hc0) & HMASK) + off;
            idx[3] = (int)((ha1 ^ hb1 ^ hc0) & HMASK) + off;
            idx[4] = (int)((ha0 ^ hb0 ^ hc1) & HMASK) + off;
            idx[5] = (int)((ha1 ^ hb0 ^ hc1) & HMASK) + off;
            idx[6] = (int)((ha0 ^ hb1 ^ hc1) & HMASK) + off;
            idx[7] = (int)((ha1 ^ hb1 ^ hc1) & HMASK) + off;
        } else {
            const int rr = res * res;
            int base = a0 + res * (b0 + res * c0) + off;
            idx[0] = base;
            idx[1] = base + 1;
            idx[2] = base + res;
            idx[3] = base + res + 1;
            idx[4] = base + rr;
            idx[5] = base + rr + 1;
            idx[6] = base + rr + res;
            idx[7] = base + rr + res + 1;
        }

        float2 f[8];
        #pragma unroll
        for (int i = 0; i < 8; ++i) f[i] = ldg_tbl(&tbl[idx[i]], pol);

        const float oma = __fsub_rn(1.0f, wa);
        const float omb = __fsub_rn(1.0f, wb);
        const float omc = __fsub_rn(1.0f, wc);
        float accx = 0.0f, accy = 0.0f;
        #pragma unroll
        for (int i = 0; i < 8; ++i) {
            float cwa = (i & 1) ? wa : oma;
            float cwb = (i & 2) ? wb : omb;
            float cwc = (i & 4) ? wc : omc;
            float cw  = __fmul_rn(__fmul_rn(cwa, cwb), cwc);
            accx = __fadd_rn(accx, __fmul_rn(f[i].x, cw));
            accy = __fadd_rn(accy, __fmul_rn(f[i].y, cw));
        }
        acc[j] = make_float2(accx, accy);
    }

    float2* optr = out + (size_t)pt * 64 + (size_t)e * 16 + L0;
    #pragma unroll
    for (int j = 0; j < NLEV; j += 2) {
        st_cs4((float4*)(optr + j),
               make_float4(acc[j].x, acc[j].y, acc[j + 1].x, acc[j + 1].y));
    }
}

// Side-stream resources, created once on the (uncaptured) correctness call.
struct ForkResources {
    cudaStream_t side;
    cudaEvent_t  ev_fork, ev_join;
    ForkResources() {
        cudaStreamCreateWithFlags(&side, cudaStreamNonBlocking);
        cudaEventCreateWithFlags(&ev_fork, cudaEventDisableTiming);
        cudaEventCreateWithFlags(&ev_join, cudaEventDisableTiming);
    }
};

extern "C" void kernel_launch(void* const* d_in, const int* in_sizes, int n_in,
                              void* d_out, int out_size) {
    static ForkResources fr;                // init on first (uncaptured) call

    const int n = in_sizes[0] / 4;          // number of points (262144)
    const float4* coords = (const float4*)d_in[0];
    const float4* refc   = (const float4*)d_in[1];
    const float2* t0 = (const float2*)d_in[2];
    const float2* t1 = (const float2*)d_in[3];
    const float2* t2 = (const float2*)d_in[4];
    const float2* t3 = (const float2*)d_in[5];
    float2* out = (float2*)d_out;

    dim3 block(256);                        // 8 warps = 2 pt-groups x 4 encodings
    dim3 grid(n / 64);

    // Fork: enc<12,4> (identity order, independent of the sort) runs on the
    // side stream concurrently with sort + perm-encodes.
    cudaEventRecord(fr.ev_fork, 0);
    cudaStreamWaitEvent(fr.side, fr.ev_fork, 0);
    energy4d_group_kernel<12, 4, false>
        <<<grid, block, 0, fr.side>>>(coords, refc, t0, t1, t2, t3, out);
    cudaEventRecord(fr.ev_join, fr.side);

    // Main chain: counting sort by 16-bit Morton key, then perm encodes.
    key_hist_kernel<<<n / 512, 256>>>(coords, refc);
    scanA_kernel<<<256, 256>>>();
    scanB_kernel<<<1, 32>>>();
    scanC_kernel<<<256, 256>>>();
    scatter_kernel<<<n / 4 / 256, 256>>>();

    energy4d_group_kernel<0,  4, true><<<grid, block>>>(coords, refc, t0, t1, t2, t3, out);
    energy4d_group_kernel<4,  4, true><<<grid, block>>>(coords, refc, t0, t1, t2, t3, out);
    energy4d_group_kernel<8,  4, true><<<grid, block>>>(coords, refc, t0, t1, t2, t3, out);

    // Join.
    cudaStreamWaitEvent(0, fr.ev_join, 0);
}

// round 17
// speedup vs baseline: 1.0731x; 1.0539x over previous
#include <cuda_runtime.h>
#include <stdint.h>

// Energy4D: 4x multi-resolution hash-grid encodings (instant-NGP style).
// L=16 levels, F=2 feats, HMAP=2^19, BASE=32, GROWTH=2 -> res_l = 32<<l.
//
// R16 -> R17: the four encode kernels are mutually independent but were
// serialized on one stream, each paying a ~0.5-wave drain tail (grid=4096
// ~= 3.5 waves). Full DAG: <12,4> from root (side1); after scatter fork
// <4,4> (side2) and <8,4> (side3) while main runs <0,4>; join all. Also
// merged scanB into scanC (each block redundantly scans the 256 block sums
// in smem) -> sort chain is 4 nodes deep instead of 5.
//
// Numerics must match XLA bit-for-bit: x/const -> x*rn(1/const);
// w = rn(u*resm1) - p0_clip; all __f*_rn (immune to --use_fast_math).

constexpr unsigned HMASK = (1u << 19) - 1u;
constexpr unsigned P1 = 2654435761u;
constexpr unsigned P2 = 805459861u;
constexpr int NPTS = 262144;
constexpr int NBINS = 65536;

__device__ int g_cnt[NBINS];    // counts: zeroed by scanC for next replay
__device__ int g_off[NBINS];    // scatter offsets (rewritten every run)
__device__ int g_bsum[256];
__device__ unsigned short g_key[NPTS];
__device__ int g_perm[NPTS];

__device__ __host__ constexpr int level_offset(int l) {
    return (l == 0) ? 0 : (l == 1) ? 32768 : 294912 + (l - 2) * 524288;
}

__device__ __forceinline__ float clip01(float v) {
    return fminf(fmaxf(v, 0.0f), 1.0f);
}

__device__ __forceinline__ float2 ldg_tbl(const float2* p, uint64_t pol) {
    float2 v;
    asm("ld.global.nc.L2::cache_hint.v2.f32 {%0,%1}, [%2], %3;"
        : "=f"(v.x), "=f"(v.y) : "l"(p), "l"(pol));
    return v;
}

__device__ __forceinline__ void st_cs4(float4* p, float4 v) {
    asm volatile("st.global.cs.v4.f32 [%0], {%1,%2,%3,%4};"
                 :: "l"(p), "f"(v.x), "f"(v.y), "f"(v.z), "f"(v.w) : "memory");
}

__device__ __forceinline__ void compute_u(float4 c, float4 r,
                                          float& ux, float& uy, float& uz, float& ut) {
    const float R180   = 1.0f / 180.0f;
    const float R360   = 1.0f / 360.0f;
    const float R20000 = 1.0f / 20000.0f;
    float nx = clip01(__fmul_rn(__fadd_rn(__fsub_rn(c.x, r.x), 90.0f),    R180));
    float ny = clip01(__fmul_rn(__fadd_rn(__fsub_rn(c.y, r.y), 180.0f),   R360));
    float nz = clip01(__fmul_rn(__fadd_rn(__fsub_rn(c.z, r.z), 11000.0f), R20000));
    float nt = clip01(__fsub_rn(c.w, r.w));
    float tsn = __fmul_rn(__fsub_rn(__fmul_rn(nt, 2.0f), 1.0f), 0.9f);
    ux = clip01(__fmul_rn(__fadd_rn(nx,  1.0f), 0.5f));
    uy = clip01(__fmul_rn(__fadd_rn(ny,  1.0f), 0.5f));
    uz = clip01(__fmul_rn(__fadd_rn(nz,  1.0f), 0.5f));
    ut = clip01(__fmul_rn(__fadd_rn(tsn, 1.0f), 0.5f));
}

// ---------------- sort: key+hist -> scanA -> scanC -> scatter -------------

__device__ __forceinline__ int quantn(float v, float lo, float inv_w, int maxq) {
    int q = (int)((v - lo) * inv_w);
    return min(max(q, 0), maxq);
}

__device__ __forceinline__ unsigned make_key(float ux, float uy, float uz, float ut) {
    // bits: x=3, y=3, z=3, t=7 (t spans ~16x more cells than x per level)
    unsigned qx = quantn(ux, 0.7444f, 8.0f   / 0.0112f, 7);
    unsigned qy = quantn(uy, 0.7472f, 8.0f   / 0.0056f, 7);
    unsigned qz = quantn(uz, 0.7700f, 8.0f   / 0.0100f, 7);
    unsigned qt = quantn(ut, 0.0500f, 128.0f / 0.1800f, 127);
    return (qt & 3u)
        | ((qx & 1u) << 2) | ((qy & 1u) << 3) | ((qz & 1u) << 4)
        | (((qt >> 2) & 3u) << 5)
        | (((qx >> 1) & 1u) << 7) | (((qy >> 1) & 1u) << 8) | (((qz >> 1) & 1u) << 9)
        | (((qt >> 4) & 3u) << 10)
        | (((qx >> 2) & 1u) << 12) | (((qy >> 2) & 1u) << 13) | (((qz >> 2) & 1u) << 14)
        | (((qt >> 6) & 1u) << 15);
}

__global__ void key_hist_kernel(const float4* __restrict__ coords,
                                const float4* __restrict__ refc) {
    int base = blockIdx.x * (blockDim.x * 2) + threadIdx.x;
    #pragma unroll
    for (int k = 0; k < 2; ++k) {
        int i = base + k * blockDim.x;
        float ux, uy, uz, ut;
        compute_u(coords[i], refc[i], ux, uy, uz, ut);
        unsigned key = make_key(ux, uy, uz, ut);
        g_key[i] = (unsigned short)key;
        atomicAdd(&g_cnt[key], 1);
    }
}

// A: per-block sums of 256-bin chunks
__global__ __launch_bounds__(256) void scanA_kernel() {
    __shared__ int s[256];
    int t = threadIdx.x;
    s[t] = g_cnt[blockIdx.x * 256 + t];
    __syncthreads();
    for (int off = 128; off > 0; off >>= 1) {
        if (t < off) s[t] += s[t + off];
        __syncthreads();
    }
    if (t == 0) g_bsum[blockIdx.x] = s[0];
}

// C: per-chunk exclusive scan + chunk offset (each block redundantly scans
// the 256 block sums in smem — replaces the separate scanB kernel);
// rezeroes g_cnt for the next graph replay.
__global__ __launch_bounds__(256) void scanC_kernel() {
    __shared__ int s[256];
    __shared__ int b[256];
    int t = threadIdx.x;
    int bin = blockIdx.x * 256 + t;
    int v = g_cnt[bin];
    g_cnt[bin] = 0;                      // restore zeros for next replay
    s[t] = v;
    b[t] = g_bsum[t];
    __syncthreads();
    int myb = b[t];
    for (int off = 1; off < 256; off <<= 1) {
        int x  = (t >= off) ? s[t - off] : 0;
        int xb = (t >= off) ? b[t - off] : 0;
        __syncthreads();
        s[t] += x;
        b[t] += xb;
        __syncthreads();
    }
    (void)myb;
    int chunk_off = (blockIdx.x == 0) ? 0 : b[blockIdx.x - 1];  // exclusive
    g_off[bin] = s[t] - v + chunk_off;
}

// scatter: 4 points per thread — independent atomic chains
__global__ void scatter_kernel() {
    int base = (blockIdx.x * blockDim.x + threadIdx.x) * 4;
    #pragma unroll
    for (int k = 0; k < 4; ++k) {
        int i = base + k;
        int pos = atomicAdd(&g_off[g_key[i]], 1);
        g_perm[pos] = i;
    }
}

// ---------------- main encode kernels ----------------

template <int L0, int NLEV, bool USE_PERM>
__global__ __launch_bounds__(256) void energy4d_group_kernel(
    const float4* __restrict__ coords,
    const float4* __restrict__ refc,
    const float2* __restrict__ t0,
    const float2* __restrict__ t1,
    const float2* __restrict__ t2,
    const float2* __restrict__ t3,
    float2* __restrict__ out)   // out as float2: elem = pt*64 + e*16 + l
{
    const int warp = threadIdx.x >> 5;
    const int lane = threadIdx.x & 31;
    const int e    = warp & 3;                               // encoding id
    const int slot = (blockIdx.x * 2 + (warp >> 2)) * 32 + lane;
    const int pt   = USE_PERM ? g_perm[slot] : slot;

    uint64_t pol;
    asm("createpolicy.fractional.L2::evict_last.b64 %0, 1.0;" : "=l"(pol));

    float ux, uy, uz, ut;
    compute_u(coords[pt], refc[pt], ux, uy, uz, ut);

    // encoding dim selection: e0=(x,y,z) e1=(x,y,t) e2=(y,z,t) e3=(x,z,t)
    const float ua = (e == 2) ? uy : ux;
    const float ub = (e <= 1) ? uy : uz;
    const float uc = (e == 0) ? uz : ut;
    const float2* __restrict__ tbl =
        (e == 0) ? t0 : (e == 1) ? t1 : (e == 2) ? t2 : t3;

    float2 acc[NLEV];

    #pragma unroll
    for (int j = 0; j < NLEV; ++j) {
        const int   l     = L0 + j;
        const int   res   = 32 << l;
        const float resm1 = (float)(res - 1);
        const int   off   = level_offset(l);

        float pa = __fmul_rn(ua, resm1);
        float pb = __fmul_rn(ub, resm1);
        float pc = __fmul_rn(uc, resm1);
        int a0 = min(max((int)floorf(pa), 0), res - 2);
        int b0 = min(max((int)floorf(pb), 0), res - 2);
        int c0 = min(max((int)floorf(pc), 0), res - 2);
        float wa = __fsub_rn(pa, (float)a0);
        float wb = __fsub_rn(pb, (float)b0);
        float wc = __fsub_rn(pc, (float)c0);

        int idx[8];
        if (l >= 2) {
            unsigned ha0 = (unsigned)a0,      ha1 = ha0 + 1u;
            unsigned hb0 = (unsigned)b0 * P1, hb1 = hb0 + P1;
            unsigned hc0 = (unsigned)c0 * P2, hc1 = hc0 + P2;
            idx[0] = (int)((ha0 ^ hb0 ^ hc0) & HMASK) + off;
            idx[1] = (int)((ha1 ^ hb0 ^ hc0) & HMASK) + off;
            idx[2] = (int)((ha0 ^ hb1 ^ hc0) & HMASK) + off;
            idx[3] = (int)((ha1 ^ hb1 ^ hc0) & HMASK) + off;
            idx[4] = (int)((ha0 ^ hb0 ^ hc1) & HMASK) + off;
            idx[5] = (int)((ha1 ^ hb0 ^ hc1) & HMASK) + off;
            idx[6] = (int)((ha0 ^ hb1 ^ hc1) & HMASK) + off;
            idx[7] = (int)((ha1 ^ hb1 ^ hc1) & HMASK) + off;
        } else {
            const int rr = res * res;
            int base = a0 + res * (b0 + res * c0) + off;
            idx[0] = base;
            idx[1] = base + 1;
            idx[2] = base + res;
            idx[3] = base + res + 1;
            idx[4] = base + rr;
            idx[5] = base + rr + 1;
            idx[6] = base + rr + res;
            idx[7] = base + rr + res + 1;
        }

        float2 f[8];
        #pragma unroll
        for (int i = 0; i < 8; ++i) f[i] = ldg_tbl(&tbl[idx[i]], pol);

        const float oma = __fsub_rn(1.0f, wa);
        const float omb = __fsub_rn(1.0f, wb);
        const float omc = __fsub_rn(1.0f, wc);
        float accx = 0.0f, accy = 0.0f;
        #pragma unroll
        for (int i = 0; i < 8; ++i) {
            float cwa = (i & 1) ? wa : oma;
            float cwb = (i & 2) ? wb : omb;
            float cwc = (i & 4) ? wc : omc;
            float cw  = __fmul_rn(__fmul_rn(cwa, cwb), cwc);
            accx = __fadd_rn(accx, __fmul_rn(f[i].x, cw));
            accy = __fadd_rn(accy, __fmul_rn(f[i].y, cw));
        }
        acc[j] = make_float2(accx, accy);
    }

    float2* optr = out + (size_t)pt * 64 + (size_t)e * 16 + L0;
    #pragma unroll
    for (int j = 0; j < NLEV; j += 2) {
        st_cs4((float4*)(optr + j),
               make_float4(acc[j].x, acc[j].y, acc[j + 1].x, acc[j + 1].y));
    }
}

// Stream/event resources, created once on the (uncaptured) correctness call.
struct ForkResources {
    cudaStream_t s1, s2, s3;
    cudaEvent_t  ev_fork, ev_scatter, ev1, ev2, ev3;
    ForkResources() {
        cudaStreamCreateWithFlags(&s1, cudaStreamNonBlocking);
        cudaStreamCreateWithFlags(&s2, cudaStreamNonBlocking);
        cudaStreamCreateWithFlags(&s3, cudaStreamNonBlocking);
        cudaEventCreateWithFlags(&ev_fork,    cudaEventDisableTiming);
        cudaEventCreateWithFlags(&ev_scatter, cudaEventDisableTiming);
        cudaEventCreateWithFlags(&ev1, cudaEventDisableTiming);
        cudaEventCreateWithFlags(&ev2, cudaEventDisableTiming);
        cudaEventCreateWithFlags(&ev3, cudaEventDisableTiming);
    }
};

extern "C" void kernel_launch(void* const* d_in, const int* in_sizes, int n_in,
                              void* d_out, int out_size) {
    static ForkResources fr;                // init on first (uncaptured) call

    const int n = in_sizes[0] / 4;          // number of points (262144)
    const float4* coords = (const float4*)d_in[0];
    const float4* refc   = (const float4*)d_in[1];
    const float2* t0 = (const float2*)d_in[2];
    const float2* t1 = (const float2*)d_in[3];
    const float2* t2 = (const float2*)d_in[4];
    const float2* t3 = (const float2*)d_in[5];
    float2* out = (float2*)d_out;

    dim3 block(256);                        // 8 warps = 2 pt-groups x 4 encodings
    dim3 grid(n / 64);

    // Root fork: enc<12,4> (identity order, independent of everything).
    cudaEventRecord(fr.ev_fork, 0);
    cudaStreamWaitEvent(fr.s1, fr.ev_fork, 0);
    energy4d_group_kernel<12, 4, false>
        <<<grid, block, 0, fr.s1>>>(coords, refc, t0, t1, t2, t3, out);
    cudaEventRecord(fr.ev1, fr.s1);

    // Main chain: counting sort (4 nodes), then fork the three perm encodes.
    key_hist_kernel<<<n / 512, 256>>>(coords, refc);
    scanA_kernel<<<256, 256>>>();
    scanC_kernel<<<256, 256>>>();
    scatter_kernel<<<n / 4 / 256, 256>>>();
    cudaEventRecord(fr.ev_scatter, 0);

    cudaStreamWaitEvent(fr.s2, fr.ev_scatter, 0);
    energy4d_group_kernel<4, 4, true>
        <<<grid, block, 0, fr.s2>>>(coords, refc, t0, t1, t2, t3, out);
    cudaEventRecord(fr.ev2, fr.s2);

    cudaStreamWaitEvent(fr.s3, fr.ev_scatter, 0);
    energy4d_group_kernel<8, 4, true>
        <<<grid, block, 0, fr.s3>>>(coords, refc, t0, t1, t2, t3, out);
    cudaEventRecord(fr.ev3, fr.s3);

    energy4d_group_kernel<0, 4, true><<<grid, block>>>(coords, refc, t0, t1, t2, t3, out);

    // Join all branches on the capture stream.
    cudaStreamWaitEvent(0, fr.ev1, 0);
    cudaStreamWaitEvent(0, fr.ev2, 0);
    cudaStreamWaitEvent(0, fr.ev3, 0);
}